// round 4
// baseline (speedup 1.0000x reference)
#include <cuda_runtime.h>

#define NB   2
#define LQ   1024
#define LIN  4096
#define CC   256
#define MH   8
#define NP   4
#define SPTS (NB*LQ*MH*NP)   /* 65536 sampling points */

#define GR   32               /* grid resolution per axis */
#define G3   (GR*GR*GR)       /* 32768 cells per batch */

// ---------------- scratch (device globals; no allocation allowed) ----------
__device__ float g_value[NB*LIN*CC];   // (B, Lin, M, D) = 8 MiB
__device__ float g_loc[SPTS*3];        // sampling locations
__device__ float g_attw[SPTS];         // softmaxed attention weights
__device__ int   g_idx[SPTS];          // 1-NN candidate index (within batch)
__device__ float g_mid[NB*LQ*CC];      // pre-output-projection features

// grid acceleration structure
__device__ float  g_glo[NB][3];        // bbox lo
__device__ float  g_gh[NB][3];         // cell size
__device__ float  g_ghinv[NB][3];      // 1/cell size
__device__ int    g_cnt[NB*G3];        // per-cell counts
__device__ int    g_cur[NB*G3];        // scatter cursors
__device__ int    g_cellStart[NB*(G3+1)];
__device__ float4 g_cpts[NB*LIN];      // sorted candidates (x,y,z, idx-bits)
__device__ int    g_pcell[NB*LIN];     // cell id per candidate

// ---------------- packed f32x2 helpers --------------------------------------
typedef unsigned long long u64;
__device__ __forceinline__ u64 pk2(float a, float b) {
    u64 r; asm("mov.b64 %0,{%1,%2};" : "=l"(r) : "f"(a), "f"(b)); return r;
}
__device__ __forceinline__ u64 ffma2(u64 a, u64 b, u64 c) {
    u64 d; asm("fma.rn.f32x2 %0,%1,%2,%3;" : "=l"(d) : "l"(a), "l"(b), "l"(c)); return d;
}
__device__ __forceinline__ float2 up2(u64 v) {
    float2 f; asm("mov.b64 {%0,%1},%2;" : "=f"(f.x), "=f"(f.y) : "l"(v)); return f;
}

// ---------------- tiled SGEMM-NT, K=256, BM=BN=64, BK=16, 256 thr, 4x4 ------
template<int EPI>
__global__ __launch_bounds__(256)
void sgemm_nt(const float* __restrict__ A,
              const float* __restrict__ W1, const float* __restrict__ W2, int wsplit,
              const float* __restrict__ b1, const float* __restrict__ b2,
              float* __restrict__ Out, int N,
              const float* __restrict__ qpts)
{
    __shared__ float As[16][68];
    __shared__ float Bs[16][68];
    const int tid = threadIdx.x;
    const int tx = tid & 15, ty = tid >> 4;
    const int rowBase = blockIdx.y * 64;
    const int colBase = blockIdx.x * 64;
    const int lr = tid >> 2;
    const int lc = (tid & 3) * 4;

    const float* Aptr = A + (rowBase + lr) * 256 + lc;
    const int wrow = colBase + lr;
    const float* Wptr = (wrow < wsplit) ? (W1 + wrow * 256 + lc)
                                        : (W2 + (wrow - wsplit) * 256 + lc);
    float4 ra = *(const float4*)Aptr;
    float4 rw = *(const float4*)Wptr;

    u64 acc[4][2];
    #pragma unroll
    for (int i = 0; i < 4; i++) { acc[i][0] = 0ull; acc[i][1] = 0ull; }

    for (int kt = 0; kt < 256; kt += 16) {
        As[lc+0][lr] = ra.x; As[lc+1][lr] = ra.y; As[lc+2][lr] = ra.z; As[lc+3][lr] = ra.w;
        Bs[lc+0][lr] = rw.x; Bs[lc+1][lr] = rw.y; Bs[lc+2][lr] = rw.z; Bs[lc+3][lr] = rw.w;
        __syncthreads();
        if (kt < 240) {
            ra = *(const float4*)(Aptr + kt + 16);
            rw = *(const float4*)(Wptr + kt + 16);
        }
        #pragma unroll
        for (int k = 0; k < 16; k++) {
            float4 av = *(const float4*)&As[k][ty * 4];
            float4 bv = *(const float4*)&Bs[k][tx * 4];
            u64 b01 = pk2(bv.x, bv.y), b23 = pk2(bv.z, bv.w);
            u64 a0 = pk2(av.x, av.x), a1 = pk2(av.y, av.y);
            u64 a2 = pk2(av.z, av.z), a3 = pk2(av.w, av.w);
            acc[0][0] = ffma2(a0, b01, acc[0][0]); acc[0][1] = ffma2(a0, b23, acc[0][1]);
            acc[1][0] = ffma2(a1, b01, acc[1][0]); acc[1][1] = ffma2(a1, b23, acc[1][1]);
            acc[2][0] = ffma2(a2, b01, acc[2][0]); acc[2][1] = ffma2(a2, b23, acc[2][1]);
            acc[3][0] = ffma2(a3, b01, acc[3][0]); acc[3][1] = ffma2(a3, b23, acc[3][1]);
        }
        __syncthreads();
    }

    const int c0 = colBase + tx * 4;
    float bias[4];
    #pragma unroll
    for (int j = 0; j < 4; j++) {
        int c = c0 + j;
        bias[j] = (c < wsplit) ? b1[c] : b2[c - wsplit];
    }

    #pragma unroll
    for (int i = 0; i < 4; i++) {
        const int r = rowBase + ty * 4 + i;
        float2 v01 = up2(acc[i][0]);
        float2 v23 = up2(acc[i][1]);
        float v[4] = { v01.x + bias[0], v01.y + bias[1],
                       v23.x + bias[2], v23.y + bias[3] };
        if (EPI == 0) {
            *(float4*)&Out[r * N + c0] = make_float4(v[0], v[1], v[2], v[3]);
        } else {
            if (c0 < 96) {
                #pragma unroll
                for (int j = 0; j < 4; j++) {
                    int c = c0 + j;
                    g_loc[r * 96 + c] = v[j] + qpts[r * 3 + (c % 3)];
                }
            } else {
                float m0 = fmaxf(fmaxf(v[0], v[1]), fmaxf(v[2], v[3]));
                float e0 = __expf(v[0] - m0), e1 = __expf(v[1] - m0);
                float e2 = __expf(v[2] - m0), e3 = __expf(v[3] - m0);
                float inv = 1.0f / (e0 + e1 + e2 + e3);
                int base = r * 32 + (c0 - 96);
                g_attw[base + 0] = e0 * inv;
                g_attw[base + 1] = e1 * inv;
                g_attw[base + 2] = e2 * inv;
                g_attw[base + 3] = e3 * inv;
            }
        }
    }
}

// ---------------- grid build ------------------------------------------------
// blocks 0-1: bbox reduce per batch. blocks 2..65: clear counts.
__global__ __launch_bounds__(1024)
void grid_prep(const float* __restrict__ ipts)
{
    const int blk = blockIdx.x, t = threadIdx.x;
    if (blk >= 2) {
        int i = (blk - 2) * 1024 + t;
        if (i < NB * G3) g_cnt[i] = 0;
        return;
    }
    const int b = blk;
    float mn[3] = {1e30f, 1e30f, 1e30f}, mx[3] = {-1e30f, -1e30f, -1e30f};
    for (int i = t; i < LIN; i += 1024) {
        const float* p = ipts + (b * LIN + i) * 3;
        #pragma unroll
        for (int a = 0; a < 3; a++) {
            float v = p[a];
            mn[a] = fminf(mn[a], v);
            mx[a] = fmaxf(mx[a], v);
        }
    }
    #pragma unroll
    for (int o = 16; o; o >>= 1)
        #pragma unroll
        for (int a = 0; a < 3; a++) {
            mn[a] = fminf(mn[a], __shfl_xor_sync(~0u, mn[a], o));
            mx[a] = fmaxf(mx[a], __shfl_xor_sync(~0u, mx[a], o));
        }
    __shared__ float smn[3][32], smx[3][32];
    if ((t & 31) == 0) {
        int w = t >> 5;
        #pragma unroll
        for (int a = 0; a < 3; a++) { smn[a][w] = mn[a]; smx[a][w] = mx[a]; }
    }
    __syncthreads();
    if (t < 32) {
        #pragma unroll
        for (int a = 0; a < 3; a++) { mn[a] = smn[a][t]; mx[a] = smx[a][t]; }
        #pragma unroll
        for (int o = 16; o; o >>= 1)
            #pragma unroll
            for (int a = 0; a < 3; a++) {
                mn[a] = fminf(mn[a], __shfl_xor_sync(~0u, mn[a], o));
                mx[a] = fmaxf(mx[a], __shfl_xor_sync(~0u, mx[a], o));
            }
        if (t == 0) {
            #pragma unroll
            for (int a = 0; a < 3; a++) {
                float lo = mn[a] - 1e-5f;
                float h  = (mx[a] - lo + 1e-5f) / GR;
                g_glo[b][a] = lo;
                g_gh[b][a] = h;
                g_ghinv[b][a] = 1.0f / h;
            }
        }
    }
}

__device__ __forceinline__ int cell_coord(float v, float lo, float hinv) {
    int c = (int)floorf((v - lo) * hinv);
    return min(GR - 1, max(0, c));
}

__global__ __launch_bounds__(256)
void grid_count(const float* __restrict__ ipts)
{
    int i = blockIdx.x * 256 + threadIdx.x;          // 0..8191
    if (i >= NB * LIN) return;
    int b = i >> 12;
    const float* p = ipts + i * 3;
    int cx = cell_coord(p[0], g_glo[b][0], g_ghinv[b][0]);
    int cy = cell_coord(p[1], g_glo[b][1], g_ghinv[b][1]);
    int cz = cell_coord(p[2], g_glo[b][2], g_ghinv[b][2]);
    int cell = (cz * GR + cy) * GR + cx;
    g_pcell[i] = cell;
    atomicAdd(&g_cnt[b * G3 + cell], 1);
}

__global__ __launch_bounds__(1024)
void grid_prefix()
{
    const int b = blockIdx.x, t = threadIdx.x;
    const int base = t * 32;
    int sum = 0;
    #pragma unroll
    for (int i = 0; i < 32; i++) sum += g_cnt[b * G3 + base + i];
    __shared__ int ss[1024];
    ss[t] = sum;
    __syncthreads();
    for (int o = 1; o < 1024; o <<= 1) {
        int v = (t >= o) ? ss[t - o] : 0;
        __syncthreads();
        ss[t] += v;
        __syncthreads();
    }
    int run = ss[t] - sum;   // exclusive prefix
    const int cb = b * (G3 + 1);
    #pragma unroll
    for (int i = 0; i < 32; i++) {
        g_cellStart[cb + base + i] = run;
        g_cur[b * G3 + base + i] = run;
        run += g_cnt[b * G3 + base + i];
    }
    if (t == 1023) g_cellStart[cb + G3] = run;
}

__global__ __launch_bounds__(256)
void grid_scatter(const float* __restrict__ ipts)
{
    int i = blockIdx.x * 256 + threadIdx.x;
    if (i >= NB * LIN) return;
    int b = i >> 12, l = i & (LIN - 1);
    int cell = g_pcell[i];
    int pos = atomicAdd(&g_cur[b * G3 + cell], 1);
    const float* p = ipts + i * 3;
    g_cpts[b * LIN + pos] = make_float4(p[0], p[1], p[2], __int_as_float(l));
}

// ---------------- grid 1-NN query -------------------------------------------
// One thread per sampling point; expanding Chebyshev shells with exact
// face-distance stopping bound. Tie-break = lowest original index (argmin).
__global__ __launch_bounds__(256)
void knn_query()
{
    const int s = blockIdx.x * 256 + threadIdx.x;    // 0..65535
    const int b = s >> 15;
    const float sx = g_loc[3*s+0], sy = g_loc[3*s+1], sz = g_loc[3*s+2];
    const float lox = g_glo[b][0], loy = g_glo[b][1], loz = g_glo[b][2];
    const float hx = g_gh[b][0], hy = g_gh[b][1], hz = g_gh[b][2];

    const int cx = cell_coord(sx, lox, g_ghinv[b][0]);
    const int cy = cell_coord(sy, loy, g_ghinv[b][1]);
    const int cz = cell_coord(sz, loz, g_ghinv[b][2]);

    const int cb = b * (G3 + 1);
    const float4* pts = g_cpts + b * LIN;

    float best = 1e30f;
    int bi = 0x7fffffff;

    auto scanCell = [&](int cell) {
        int st = g_cellStart[cb + cell];
        int en = g_cellStart[cb + cell + 1];
        for (int k = st; k < en; k++) {
            float4 p = pts[k];
            float dx = p.x - sx, dy = p.y - sy, dz = p.z - sz;
            float d = fmaf(dx, dx, fmaf(dy, dy, dz * dz));
            int pi = __float_as_int(p.w);
            if (d < best || (d == best && pi < bi)) { best = d; bi = pi; }
        }
    };

    for (int r = 0; r < GR; r++) {
        const int x0 = max(cx - r, 0), x1 = min(cx + r, GR - 1);
        const int y0 = max(cy - r, 0), y1 = min(cy + r, GR - 1);
        const int z0 = max(cz - r, 0), z1 = min(cz + r, GR - 1);
        for (int zz = z0; zz <= z1; zz++) {
            bool fz = (zz == cz - r) || (zz == cz + r);
            for (int yy = y0; yy <= y1; yy++) {
                bool fy = fz || (yy == cy - r) || (yy == cy + r);
                int rowb = (zz * GR + yy) * GR;
                if (fy) {
                    for (int xx = x0; xx <= x1; xx++) scanCell(rowb + xx);
                } else {
                    if (cx - r >= 0)  scanCell(rowb + cx - r);
                    if (cx + r < GR)  scanCell(rowb + cx + r);
                }
            }
        }
        // exact stopping bound: distance to nearest unscanned face plane
        float dmin = 1e30f;
        if (cx - r > 0)      dmin = fminf(dmin, sx - (lox + (cx - r) * hx));
        if (cx + r < GR - 1) dmin = fminf(dmin, (lox + (cx + r + 1) * hx) - sx);
        if (cy - r > 0)      dmin = fminf(dmin, sy - (loy + (cy - r) * hy));
        if (cy + r < GR - 1) dmin = fminf(dmin, (loy + (cy + r + 1) * hy) - sy);
        if (cz - r > 0)      dmin = fminf(dmin, sz - (loz + (cz - r) * hz));
        if (cz + r < GR - 1) dmin = fminf(dmin, (loz + (cz + r + 1) * hz) - sz);
        if (dmin >= 1e30f) break;                 // whole grid scanned
        dmin = fmaxf(dmin, 0.0f);
        if (best < dmin * dmin) break;            // no outside point can win
    }
    g_idx[s] = bi;
}

// ---------------- gather + weighted sum over P -------------------------------
__global__ __launch_bounds__(256)
void gather_kernel()
{
    const int g    = (blockIdx.x * 256 + threadIdx.x) >> 5;  // bq*8 + m
    const int lane = threadIdx.x & 31;
    const int m  = g & 7;
    const int bq = g >> 3;
    const int b  = bq >> 10;
    const int base = bq * 32 + m * 4;
    float acc = 0.0f;
    #pragma unroll
    for (int p = 0; p < 4; p++) {
        int sp = base + p;
        int l = g_idx[sp];
        acc += g_attw[sp] * g_value[(b * LIN + l) * CC + m * 32 + lane];
    }
    g_mid[bq * CC + m * 32 + lane] = acc;
}

// ---------------------------------------------------------------------------
extern "C" void kernel_launch(void* const* d_in, const int* in_sizes, int n_in,
                              void* d_out, int out_size) {
    const float* query = (const float*)d_in[0];
    const float* qpts  = (const float*)d_in[1];
    const float* inp   = (const float*)d_in[2];
    const float* ipts  = (const float*)d_in[3];
    const float* Wv    = (const float*)d_in[4];
    const float* bv    = (const float*)d_in[5];
    const float* Ws    = (const float*)d_in[6];
    const float* bs    = (const float*)d_in[7];
    const float* Wa    = (const float*)d_in[8];
    const float* ba    = (const float*)d_in[9];
    const float* Wo    = (const float*)d_in[10];
    const float* bo    = (const float*)d_in[11];
    float* out = (float*)d_out;

    float *p_value, *p_mid;
    cudaGetSymbolAddress((void**)&p_value, g_value);
    cudaGetSymbolAddress((void**)&p_mid,   g_mid);

    const int BIG = 1 << 30;

    // grid build for 1-NN (independent of projections)
    grid_prep<<<2 + (NB*G3 + 1023)/1024, 1024>>>(ipts);
    grid_count<<<(NB*LIN + 255)/256, 256>>>(ipts);
    grid_prefix<<<NB, 1024>>>();
    grid_scatter<<<(NB*LIN + 255)/256, 256>>>(ipts);

    // fused sampling-offset + attention projection (writes g_loc / g_attw)
    sgemm_nt<1><<<dim3(2, 32), 256>>>(query, Ws, Wa, 96, bs, ba,
                                      nullptr, 128, qpts);
    // grid-accelerated exact 1-NN
    knn_query<<<SPTS/256, 256>>>();

    // value projection
    sgemm_nt<0><<<dim3(4, 128), 256>>>(inp, Wv, Wv, BIG, bv, bv,
                                       p_value, 256, nullptr);
    // gather + weighted sum
    gather_kernel<<<2048, 256>>>();
    // output projection
    sgemm_nt<0><<<dim3(4, 32), 256>>>(p_mid, Wo, Wo, BIG, bo, bo,
                                      out, 256, nullptr);
}

// round 5
// speedup vs baseline: 1.7780x; 1.7780x over previous
#include <cuda_runtime.h>

#define NB   2
#define LQ   1024
#define LIN  4096
#define CC   256
#define MH   8
#define NP   4
#define SPTS (NB*LQ*MH*NP)   /* 65536 sampling points */

#define GR   32
#define G3   (GR*GR*GR)      /* 32768 cells per batch */

// ---------------- scratch (device globals; no allocation allowed) ----------
__device__ float  g_value[NB*LIN*CC];  // (B, Lin, M, D) = 8 MiB
__device__ float  g_loc[SPTS*3];
__device__ float  g_attw[SPTS];
__device__ int    g_idx[SPTS];
__device__ float  g_mid[NB*LQ*CC];
__device__ float  g_glo[NB][3];
__device__ float  g_gh[NB][3];
__device__ float  g_ghinv[NB][3];
__device__ int    g_cellStart[NB*(G3+1)];
__device__ float4 g_cpts[NB*LIN];      // (x,y,z, idx-bits), cell-sorted

// ---------------- packed f32x2 helpers --------------------------------------
typedef unsigned long long u64;
__device__ __forceinline__ u64 pk2(float a, float b) {
    u64 r; asm("mov.b64 %0,{%1,%2};" : "=l"(r) : "f"(a), "f"(b)); return r;
}
__device__ __forceinline__ u64 ffma2(u64 a, u64 b, u64 c) {
    u64 d; asm("fma.rn.f32x2 %0,%1,%2,%3;" : "=l"(d) : "l"(a), "l"(b), "l"(c)); return d;
}
__device__ __forceinline__ float2 up2(u64 v) {
    float2 f; asm("mov.b64 {%0,%1},%2;" : "=f"(f.x), "=f"(f.y) : "l"(v)); return f;
}

// ---------------- tiled SGEMM-NT, K=256, BM=BN=64, BK=16, 256 thr, 4x4 ------
template<int EPI>
__global__ __launch_bounds__(256)
void sgemm_nt(const float* __restrict__ A,
              const float* __restrict__ W1, const float* __restrict__ W2, int wsplit,
              const float* __restrict__ b1, const float* __restrict__ b2,
              float* __restrict__ Out, int N,
              const float* __restrict__ qpts)
{
    __shared__ float As[16][68];
    __shared__ float Bs[16][68];
    const int tid = threadIdx.x;
    const int tx = tid & 15, ty = tid >> 4;
    const int rowBase = blockIdx.y * 64;
    const int colBase = blockIdx.x * 64;
    const int lr = tid >> 2;
    const int lc = (tid & 3) * 4;

    const float* Aptr = A + (rowBase + lr) * 256 + lc;
    const int wrow = colBase + lr;
    const float* Wptr = (wrow < wsplit) ? (W1 + wrow * 256 + lc)
                                        : (W2 + (wrow - wsplit) * 256 + lc);
    float4 ra = *(const float4*)Aptr;
    float4 rw = *(const float4*)Wptr;

    u64 acc[4][2];
    #pragma unroll
    for (int i = 0; i < 4; i++) { acc[i][0] = 0ull; acc[i][1] = 0ull; }

    for (int kt = 0; kt < 256; kt += 16) {
        As[lc+0][lr] = ra.x; As[lc+1][lr] = ra.y; As[lc+2][lr] = ra.z; As[lc+3][lr] = ra.w;
        Bs[lc+0][lr] = rw.x; Bs[lc+1][lr] = rw.y; Bs[lc+2][lr] = rw.z; Bs[lc+3][lr] = rw.w;
        __syncthreads();
        if (kt < 240) {
            ra = *(const float4*)(Aptr + kt + 16);
            rw = *(const float4*)(Wptr + kt + 16);
        }
        #pragma unroll
        for (int k = 0; k < 16; k++) {
            float4 av = *(const float4*)&As[k][ty * 4];
            float4 bv = *(const float4*)&Bs[k][tx * 4];
            u64 b01 = pk2(bv.x, bv.y), b23 = pk2(bv.z, bv.w);
            u64 a0 = pk2(av.x, av.x), a1 = pk2(av.y, av.y);
            u64 a2 = pk2(av.z, av.z), a3 = pk2(av.w, av.w);
            acc[0][0] = ffma2(a0, b01, acc[0][0]); acc[0][1] = ffma2(a0, b23, acc[0][1]);
            acc[1][0] = ffma2(a1, b01, acc[1][0]); acc[1][1] = ffma2(a1, b23, acc[1][1]);
            acc[2][0] = ffma2(a2, b01, acc[2][0]); acc[2][1] = ffma2(a2, b23, acc[2][1]);
            acc[3][0] = ffma2(a3, b01, acc[3][0]); acc[3][1] = ffma2(a3, b23, acc[3][1]);
        }
        __syncthreads();
    }

    const int c0 = colBase + tx * 4;
    float bias[4];
    #pragma unroll
    for (int j = 0; j < 4; j++) {
        int c = c0 + j;
        bias[j] = (c < wsplit) ? b1[c] : b2[c - wsplit];
    }

    #pragma unroll
    for (int i = 0; i < 4; i++) {
        const int r = rowBase + ty * 4 + i;
        float2 v01 = up2(acc[i][0]);
        float2 v23 = up2(acc[i][1]);
        float v[4] = { v01.x + bias[0], v01.y + bias[1],
                       v23.x + bias[2], v23.y + bias[3] };
        if (EPI == 0) {
            *(float4*)&Out[r * N + c0] = make_float4(v[0], v[1], v[2], v[3]);
        } else {
            if (c0 < 96) {
                #pragma unroll
                for (int j = 0; j < 4; j++) {
                    int c = c0 + j;
                    g_loc[r * 96 + c] = v[j] + qpts[r * 3 + (c % 3)];
                }
            } else {
                float m0 = fmaxf(fmaxf(v[0], v[1]), fmaxf(v[2], v[3]));
                float e0 = __expf(v[0] - m0), e1 = __expf(v[1] - m0);
                float e2 = __expf(v[2] - m0), e3 = __expf(v[3] - m0);
                float inv = 1.0f / (e0 + e1 + e2 + e3);
                int base = r * 32 + (c0 - 96);
                g_attw[base + 0] = e0 * inv;
                g_attw[base + 1] = e1 * inv;
                g_attw[base + 2] = e2 * inv;
                g_attw[base + 3] = e3 * inv;
            }
        }
    }
}

// ---------------- fused grid build: one block per batch ---------------------
// Dynamic smem: padded counts array (pad 1 word per 32 to kill prefix-pass
// bank conflicts).  idx(c) = c + (c>>5).
#define CPAD(c) ((c) + ((c) >> 5))
#define CNT_WORDS (G3 + (G3 >> 5))

extern __shared__ int s_cnt[];

__device__ __forceinline__ int cell_of(float v, float lo, float hinv) {
    int c = (int)floorf((v - lo) * hinv);
    return min(GR - 1, max(0, c));
}

__global__ __launch_bounds__(512)
void grid_build(const float* __restrict__ ipts)
{
    const int b = blockIdx.x, t = threadIdx.x;
    const int w = t >> 5, l = t & 31;

    // 1) load 8 pts/thread, bbox reduce
    float px[8], py[8], pz[8];
    float mnx = 1e30f, mny = 1e30f, mnz = 1e30f;
    float mxx = -1e30f, mxy = -1e30f, mxz = -1e30f;
    #pragma unroll
    for (int j = 0; j < 8; j++) {
        const float* p = ipts + (b*LIN + t + j*512) * 3;
        px[j] = p[0]; py[j] = p[1]; pz[j] = p[2];
        mnx = fminf(mnx, px[j]); mxx = fmaxf(mxx, px[j]);
        mny = fminf(mny, py[j]); mxy = fmaxf(mxy, py[j]);
        mnz = fminf(mnz, pz[j]); mxz = fmaxf(mxz, pz[j]);
    }
    #pragma unroll
    for (int o = 16; o; o >>= 1) {
        mnx = fminf(mnx, __shfl_xor_sync(~0u, mnx, o)); mxx = fmaxf(mxx, __shfl_xor_sync(~0u, mxx, o));
        mny = fminf(mny, __shfl_xor_sync(~0u, mny, o)); mxy = fmaxf(mxy, __shfl_xor_sync(~0u, mxy, o));
        mnz = fminf(mnz, __shfl_xor_sync(~0u, mnz, o)); mxz = fmaxf(mxz, __shfl_xor_sync(~0u, mxz, o));
    }
    __shared__ float red[6][16];
    __shared__ float box[9];     // lo3, h3, hinv3
    if (l == 0) {
        red[0][w] = mnx; red[1][w] = mny; red[2][w] = mnz;
        red[3][w] = mxx; red[4][w] = mxy; red[5][w] = mxz;
    }
    __syncthreads();
    if (t == 0) {
        float mn[3], mx[3];
        #pragma unroll
        for (int a = 0; a < 3; a++) { mn[a] = red[a][0]; mx[a] = red[3+a][0]; }
        for (int i = 1; i < 16; i++)
            #pragma unroll
            for (int a = 0; a < 3; a++) {
                mn[a] = fminf(mn[a], red[a][i]);
                mx[a] = fmaxf(mx[a], red[3+a][i]);
            }
        #pragma unroll
        for (int a = 0; a < 3; a++) {
            float lo = mn[a] - 1e-5f;
            float h  = (mx[a] - lo + 1e-5f) / GR;
            box[a] = lo; box[3+a] = h; box[6+a] = 1.0f / h;
            g_glo[b][a] = lo; g_gh[b][a] = h; g_ghinv[b][a] = 1.0f / h;
        }
    }
    __syncthreads();

    // 2) zero counts
    for (int i = t; i < CNT_WORDS; i += 512) s_cnt[i] = 0;
    __syncthreads();

    // 3) count
    int cell[8];
    #pragma unroll
    for (int j = 0; j < 8; j++) {
        int cx = cell_of(px[j], box[0], box[6]);
        int cy = cell_of(py[j], box[1], box[7]);
        int cz = cell_of(pz[j], box[2], box[8]);
        cell[j] = (cz * GR + cy) * GR + cx;
        atomicAdd(&s_cnt[CPAD(cell[j])], 1);
    }
    __syncthreads();

    // 4) exclusive prefix: 64 cells/thread + block scan of partials
    const int base = t * 64;
    int sum = 0;
    for (int i = 0; i < 64; i++) sum += s_cnt[CPAD(base + i)];
    int inc = sum;
    #pragma unroll
    for (int o = 1; o < 32; o <<= 1) {
        int v = __shfl_up_sync(~0u, inc, o);
        if (l >= o) inc += v;
    }
    __shared__ int wtot[16];
    if (l == 31) wtot[w] = inc;
    __syncthreads();
    if (t == 0) {
        int run = 0;
        for (int i = 0; i < 16; i++) { int v = wtot[i]; wtot[i] = run; run += v; }
    }
    __syncthreads();
    int run = inc - sum + wtot[w];       // exclusive start of this thread's chunk
    const int cb = b * (G3 + 1);
    for (int i = 0; i < 64; i++) {
        int c = s_cnt[CPAD(base + i)];
        g_cellStart[cb + base + i] = run;
        s_cnt[CPAD(base + i)] = run;     // becomes scatter cursor
        run += c;
    }
    if (t == 511) g_cellStart[cb + G3] = run;
    __syncthreads();

    // 5) scatter (cell-sorted candidate array)
    #pragma unroll
    for (int j = 0; j < 8; j++) {
        int i = t + j * 512;
        int pos = atomicAdd(&s_cnt[CPAD(cell[j])], 1);
        g_cpts[b*LIN + pos] = make_float4(px[j], py[j], pz[j], __int_as_float(i));
    }
}

// ---------------- grid 1-NN query: warp-uniform control flow ----------------
// One thread per sampling point. Radius loop is warp-synchronous; finished
// lanes are predicated off. Rows scanned as contiguous candidate runs.
__global__ __launch_bounds__(256)
void knn_query()
{
    const int s = blockIdx.x * 256 + threadIdx.x;
    const int b = s >> 15;
    const float sx = g_loc[3*s+0], sy = g_loc[3*s+1], sz = g_loc[3*s+2];
    const float lox = g_glo[b][0], loy = g_glo[b][1], loz = g_glo[b][2];
    const float hx = g_gh[b][0],  hy = g_gh[b][1],  hz = g_gh[b][2];
    const int cx = cell_of(sx, lox, g_ghinv[b][0]);
    const int cy = cell_of(sy, loy, g_ghinv[b][1]);
    const int cz = cell_of(sz, loz, g_ghinv[b][2]);

    const int cb = b * (G3 + 1);
    const float4* __restrict__ pts = g_cpts + b * LIN;

    float best = 1e30f;
    int bi = 0x7fffffff;
    bool done = false;

    auto scanRun = [&](int c0, int c1) {   // inclusive cell range within a row
        int st = __ldg(&g_cellStart[cb + c0]);
        int en = __ldg(&g_cellStart[cb + c1 + 1]);
        for (int k = st; k < en; k++) {
            float4 p = __ldg(&pts[k]);
            float dx = p.x - sx, dy = p.y - sy, dz = p.z - sz;
            float d = fmaf(dx, dx, fmaf(dy, dy, dz * dz));
            int pi = __float_as_int(p.w);
            if (d < best || (d == best && pi < bi)) { best = d; bi = pi; }
        }
    };

    for (int r = 1; r <= GR; r++) {        // warp-uniform
        if (!done) {
            // scan box(r) \ box(r-1)   (box(0) empty: r==1 scans full box)
            for (int idz = -r; idz <= r; idz++) {
                int zz = cz + idz;
                if (zz < 0 || zz >= GR) continue;
                for (int idy = -r; idy <= r; idy++) {
                    int yy = cy + idy;
                    if (yy < 0 || yy >= GR) continue;
                    int rowb = (zz * GR + yy) * GR;
                    bool interior = (r > 1) && (idz > -r && idz < r)
                                             && (idy > -r && idy < r);
                    if (!interior) {
                        int xa = max(cx - r, 0), xb = min(cx + r, GR - 1);
                        scanRun(rowb + xa, rowb + xb);
                    } else {
                        if (cx - r >= 0) scanRun(rowb + cx - r, rowb + cx - r);
                        if (cx + r < GR) scanRun(rowb + cx + r, rowb + cx + r);
                    }
                }
            }
            // exact stopping bound for the radius-r box
            float dmin = 1e30f;
            if (cx - r > 0)      dmin = fminf(dmin, sx - (lox + (cx - r) * hx));
            if (cx + r < GR - 1) dmin = fminf(dmin, (lox + (cx + r + 1) * hx) - sx);
            if (cy - r > 0)      dmin = fminf(dmin, sy - (loy + (cy - r) * hy));
            if (cy + r < GR - 1) dmin = fminf(dmin, (loy + (cy + r + 1) * hy) - sy);
            if (cz - r > 0)      dmin = fminf(dmin, sz - (loz + (cz - r) * hz));
            if (cz + r < GR - 1) dmin = fminf(dmin, (loz + (cz + r + 1) * hz) - sz);
            dmin = fmaxf(dmin, 0.0f);
            done = (best < dmin * dmin);   // dmin==1e30 => true (full grid scanned)
        }
        if (__all_sync(0xffffffffu, done)) break;
    }
    g_idx[s] = bi;
}

// ---------------- gather + weighted sum over P -------------------------------
__global__ __launch_bounds__(256)
void gather_kernel()
{
    const int g    = (blockIdx.x * 256 + threadIdx.x) >> 5;  // bq*8 + m
    const int lane = threadIdx.x & 31;
    const int m  = g & 7;
    const int bq = g >> 3;
    const int b  = bq >> 10;
    const int base = bq * 32 + m * 4;
    float acc = 0.0f;
    #pragma unroll
    for (int p = 0; p < 4; p++) {
        int sp = base + p;
        int l = g_idx[sp];
        acc += g_attw[sp] * g_value[(b * LIN + l) * CC + m * 32 + lane];
    }
    g_mid[bq * CC + m * 32 + lane] = acc;
}

// ---------------------------------------------------------------------------
extern "C" void kernel_launch(void* const* d_in, const int* in_sizes, int n_in,
                              void* d_out, int out_size) {
    const float* query = (const float*)d_in[0];
    const float* qpts  = (const float*)d_in[1];
    const float* inp   = (const float*)d_in[2];
    const float* ipts  = (const float*)d_in[3];
    const float* Wv    = (const float*)d_in[4];
    const float* bv    = (const float*)d_in[5];
    const float* Ws    = (const float*)d_in[6];
    const float* bs    = (const float*)d_in[7];
    const float* Wa    = (const float*)d_in[8];
    const float* ba    = (const float*)d_in[9];
    const float* Wo    = (const float*)d_in[10];
    const float* bo    = (const float*)d_in[11];
    float* out = (float*)d_out;

    float *p_value, *p_mid;
    cudaGetSymbolAddress((void**)&p_value, g_value);
    cudaGetSymbolAddress((void**)&p_mid,   g_mid);

    const int BIG = 1 << 30;
    const int smemBytes = CNT_WORDS * sizeof(int);
    static int attrSet = 0;
    if (!attrSet) {
        cudaFuncSetAttribute(grid_build,
                             cudaFuncAttributeMaxDynamicSharedMemorySize, smemBytes);
        attrSet = 1;
    }

    // 1) fused grid build (one block per batch)
    grid_build<<<NB, 512, smemBytes>>>(ipts);
    // 2) fused sampling-offset + attention projection (writes g_loc / g_attw)
    sgemm_nt<1><<<dim3(2, 32), 256>>>(query, Ws, Wa, 96, bs, ba,
                                      nullptr, 128, qpts);
    // 3) grid-accelerated exact 1-NN (warp-uniform)
    knn_query<<<SPTS/256, 256>>>();
    // 4) value projection
    sgemm_nt<0><<<dim3(4, 128), 256>>>(inp, Wv, Wv, BIG, bv, bv,
                                       p_value, 256, nullptr);
    // 5) gather + weighted sum
    gather_kernel<<<2048, 256>>>();
    // 6) output projection
    sgemm_nt<0><<<dim3(4, 32), 256>>>(p_mid, Wo, Wo, BIG, bo, bo,
                                      out, 256, nullptr);
}

// round 6
// speedup vs baseline: 4.1334x; 2.3248x over previous
#include <cuda_runtime.h>

#define NB   2
#define LQ   1024
#define LIN  4096
#define CC   256
#define MH   8
#define NP   4
#define SPTS (NB*LQ*MH*NP)   /* 65536 sampling points */

// ---------------- scratch (device globals; no allocation allowed) ----------
__device__ float g_value[NB*LIN*CC];   // (B, Lin, M, D) = 8 MiB
__device__ float g_loc[SPTS*3];        // sampling locations
__device__ float g_attw[SPTS];         // softmaxed attention weights
__device__ float g_bd[2][SPTS];        // per-half best distance
__device__ int   g_bi[2][SPTS];        // per-half best index
__device__ float g_mid[NB*LQ*CC];      // pre-output-projection features

// ---------------- packed f32x2 helpers --------------------------------------
typedef unsigned long long u64;
__device__ __forceinline__ u64 pk2(float a, float b) {
    u64 r; asm("mov.b64 %0,{%1,%2};" : "=l"(r) : "f"(a), "f"(b)); return r;
}
__device__ __forceinline__ u64 ffma2(u64 a, u64 b, u64 c) {
    u64 d; asm("fma.rn.f32x2 %0,%1,%2,%3;" : "=l"(d) : "l"(a), "l"(b), "l"(c)); return d;
}
__device__ __forceinline__ float2 up2(u64 v) {
    float2 f; asm("mov.b64 {%0,%1},%2;" : "=f"(f.x), "=f"(f.y) : "l"(v)); return f;
}

// ---------------- tiled SGEMM-NT 64x64, K=256, BK=16, 256 thr, 4x4 ----------
// (used for the small GEMMs: proj 2048x128, out 2048x256)
template<int EPI>
__global__ __launch_bounds__(256)
void sgemm_nt(const float* __restrict__ A,
              const float* __restrict__ W1, const float* __restrict__ W2, int wsplit,
              const float* __restrict__ b1, const float* __restrict__ b2,
              float* __restrict__ Out, int N,
              const float* __restrict__ qpts)
{
    __shared__ float As[16][68];
    __shared__ float Bs[16][68];
    const int tid = threadIdx.x;
    const int tx = tid & 15, ty = tid >> 4;
    const int rowBase = blockIdx.y * 64;
    const int colBase = blockIdx.x * 64;
    const int lr = tid >> 2;
    const int lc = (tid & 3) * 4;

    const float* Aptr = A + (rowBase + lr) * 256 + lc;
    const int wrow = colBase + lr;
    const float* Wptr = (wrow < wsplit) ? (W1 + wrow * 256 + lc)
                                        : (W2 + (wrow - wsplit) * 256 + lc);
    float4 ra = *(const float4*)Aptr;
    float4 rw = *(const float4*)Wptr;

    u64 acc[4][2];
    #pragma unroll
    for (int i = 0; i < 4; i++) { acc[i][0] = 0ull; acc[i][1] = 0ull; }

    for (int kt = 0; kt < 256; kt += 16) {
        As[lc+0][lr] = ra.x; As[lc+1][lr] = ra.y; As[lc+2][lr] = ra.z; As[lc+3][lr] = ra.w;
        Bs[lc+0][lr] = rw.x; Bs[lc+1][lr] = rw.y; Bs[lc+2][lr] = rw.z; Bs[lc+3][lr] = rw.w;
        __syncthreads();
        if (kt < 240) {
            ra = *(const float4*)(Aptr + kt + 16);
            rw = *(const float4*)(Wptr + kt + 16);
        }
        #pragma unroll
        for (int k = 0; k < 16; k++) {
            float4 av = *(const float4*)&As[k][ty * 4];
            float4 bv = *(const float4*)&Bs[k][tx * 4];
            u64 b01 = pk2(bv.x, bv.y), b23 = pk2(bv.z, bv.w);
            u64 a0 = pk2(av.x, av.x), a1 = pk2(av.y, av.y);
            u64 a2 = pk2(av.z, av.z), a3 = pk2(av.w, av.w);
            acc[0][0] = ffma2(a0, b01, acc[0][0]); acc[0][1] = ffma2(a0, b23, acc[0][1]);
            acc[1][0] = ffma2(a1, b01, acc[1][0]); acc[1][1] = ffma2(a1, b23, acc[1][1]);
            acc[2][0] = ffma2(a2, b01, acc[2][0]); acc[2][1] = ffma2(a2, b23, acc[2][1]);
            acc[3][0] = ffma2(a3, b01, acc[3][0]); acc[3][1] = ffma2(a3, b23, acc[3][1]);
        }
        __syncthreads();
    }

    const int c0 = colBase + tx * 4;
    float bias[4];
    #pragma unroll
    for (int j = 0; j < 4; j++) {
        int c = c0 + j;
        bias[j] = (c < wsplit) ? b1[c] : b2[c - wsplit];
    }

    #pragma unroll
    for (int i = 0; i < 4; i++) {
        const int r = rowBase + ty * 4 + i;
        float2 v01 = up2(acc[i][0]);
        float2 v23 = up2(acc[i][1]);
        float v[4] = { v01.x + bias[0], v01.y + bias[1],
                       v23.x + bias[2], v23.y + bias[3] };
        if (EPI == 0) {
            *(float4*)&Out[r * N + c0] = make_float4(v[0], v[1], v[2], v[3]);
        } else {
            if (c0 < 96) {
                #pragma unroll
                for (int j = 0; j < 4; j++) {
                    int c = c0 + j;
                    g_loc[r * 96 + c] = v[j] + qpts[r * 3 + (c % 3)];
                }
            } else {
                float m0 = fmaxf(fmaxf(v[0], v[1]), fmaxf(v[2], v[3]));
                float e0 = __expf(v[0] - m0), e1 = __expf(v[1] - m0);
                float e2 = __expf(v[2] - m0), e3 = __expf(v[3] - m0);
                float inv = 1.0f / (e0 + e1 + e2 + e3);
                int base = r * 32 + (c0 - 96);
                g_attw[base + 0] = e0 * inv;
                g_attw[base + 1] = e1 * inv;
                g_attw[base + 2] = e2 * inv;
                g_attw[base + 3] = e3 * inv;
            }
        }
    }
}

// ---------------- tiled SGEMM-NT 128x128, K=256, BK=16, 256 thr, 8x8 --------
// 2B smem traffic per FFMA2: LDS-BW and FMA pipes balanced. Used for the
// big value GEMM (grid 2x64 = 128 blocks = one full wave).
__global__ __launch_bounds__(256)
void sgemm128(const float* __restrict__ A, const float* __restrict__ W,
              const float* __restrict__ bias, float* __restrict__ Out, int N)
{
    __shared__ float As[16][128];
    __shared__ float Bs[16][128];
    const int tid = threadIdx.x;
    const int tx = tid & 15;          // col group: cols tx*8..+7
    const int ty = tid >> 4;          // row group: rows ty*8..+7
    const int rowBase = blockIdx.y * 128;
    const int colBase = blockIdx.x * 128;

    const int lr = tid >> 1;          // 0..127
    const int lk = (tid & 1) * 8;     // 0 or 8
    const float* Aptr = A + (rowBase + lr) * 256 + lk;
    const float* Wptr = W + (colBase + lr) * 256 + lk;
    float4 ra0 = *(const float4*)Aptr;
    float4 ra1 = *(const float4*)(Aptr + 4);
    float4 rw0 = *(const float4*)Wptr;
    float4 rw1 = *(const float4*)(Wptr + 4);

    u64 acc[8][4];
    #pragma unroll
    for (int i = 0; i < 8; i++)
        #pragma unroll
        for (int j = 0; j < 4; j++) acc[i][j] = 0ull;

    for (int kt = 0; kt < 256; kt += 16) {
        As[lk+0][lr] = ra0.x; As[lk+1][lr] = ra0.y; As[lk+2][lr] = ra0.z; As[lk+3][lr] = ra0.w;
        As[lk+4][lr] = ra1.x; As[lk+5][lr] = ra1.y; As[lk+6][lr] = ra1.z; As[lk+7][lr] = ra1.w;
        Bs[lk+0][lr] = rw0.x; Bs[lk+1][lr] = rw0.y; Bs[lk+2][lr] = rw0.z; Bs[lk+3][lr] = rw0.w;
        Bs[lk+4][lr] = rw1.x; Bs[lk+5][lr] = rw1.y; Bs[lk+6][lr] = rw1.z; Bs[lk+7][lr] = rw1.w;
        __syncthreads();
        if (kt < 240) {
            ra0 = *(const float4*)(Aptr + kt + 16);
            ra1 = *(const float4*)(Aptr + kt + 20);
            rw0 = *(const float4*)(Wptr + kt + 16);
            rw1 = *(const float4*)(Wptr + kt + 20);
        }
        #pragma unroll
        for (int k = 0; k < 16; k++) {
            float4 a0 = *(const float4*)&As[k][ty * 8];
            float4 a1 = *(const float4*)&As[k][ty * 8 + 4];
            float4 b0 = *(const float4*)&Bs[k][tx * 8];
            float4 b1 = *(const float4*)&Bs[k][tx * 8 + 4];
            u64 bp[4] = { pk2(b0.x, b0.y), pk2(b0.z, b0.w),
                          pk2(b1.x, b1.y), pk2(b1.z, b1.w) };
            float av[8] = { a0.x, a0.y, a0.z, a0.w, a1.x, a1.y, a1.z, a1.w };
            #pragma unroll
            for (int i = 0; i < 8; i++) {
                u64 ap = pk2(av[i], av[i]);
                #pragma unroll
                for (int j = 0; j < 4; j++)
                    acc[i][j] = ffma2(ap, bp[j], acc[i][j]);
            }
        }
        __syncthreads();
    }

    const int c0 = colBase + tx * 8;
    float4 bia0 = *(const float4*)&bias[c0];
    float4 bia1 = *(const float4*)&bias[c0 + 4];
    #pragma unroll
    for (int i = 0; i < 8; i++) {
        const int r = rowBase + ty * 8 + i;
        float2 v0 = up2(acc[i][0]), v1 = up2(acc[i][1]);
        float2 v2 = up2(acc[i][2]), v3 = up2(acc[i][3]);
        *(float4*)&Out[r * N + c0] =
            make_float4(v0.x + bia0.x, v0.y + bia0.y, v1.x + bia0.z, v1.y + bia0.w);
        *(float4*)&Out[r * N + c0 + 4] =
            make_float4(v2.x + bia1.x, v2.y + bia1.y, v3.x + bia1.z, v3.y + bia1.w);
    }
}

// ---------------- brute-force 1-NN, candidate-split halves ------------------
__global__ __launch_bounds__(256)
void knn_kernel(const float* __restrict__ ipts)
{
    __shared__ __align__(16) float xs[2048];
    __shared__ __align__(16) float ys[2048];
    __shared__ __align__(16) float zs[2048];
    __shared__ __align__(16) float wsq[2048];

    const int tid  = threadIdx.x;
    const int sblk = blockIdx.x >> 1;
    const int half = blockIdx.x & 1;
    const int sbase = sblk * 1024;
    const int b = sbase >> 15;
    const int cbase = b * LIN + half * 2048;

    for (int i = tid; i < 2048; i += 256) {
        float x = ipts[(cbase + i) * 3 + 0];
        float y = ipts[(cbase + i) * 3 + 1];
        float z = ipts[(cbase + i) * 3 + 2];
        xs[i] = x; ys[i] = y; zs[i] = z;
        wsq[i] = x * x + y * y + z * z;
    }
    __syncthreads();

    int   s[4], bi[4];
    float best[4];
    u64 ax2[4], ay2[4], az2[4];
    #pragma unroll
    for (int k = 0; k < 4; k++) {
        s[k] = sbase + k * 256 + tid;
        float sx = g_loc[3 * s[k] + 0];
        float sy = g_loc[3 * s[k] + 1];
        float sz = g_loc[3 * s[k] + 2];
        float ax = -2.0f * sx, ay = -2.0f * sy, az = -2.0f * sz;
        ax2[k] = pk2(ax, ax); ay2[k] = pk2(ay, ay); az2[k] = pk2(az, az);
        best[k] = 3.4e38f; bi[k] = 0;
    }

    const u64* X = (const u64*)xs;
    const u64* Y = (const u64*)ys;
    const u64* Z = (const u64*)zs;
    const u64* Wv = (const u64*)wsq;

    #pragma unroll 4
    for (int j = 0; j < 1024; j++) {
        u64 xv = X[j], yv = Y[j], zv = Z[j], wv = Wv[j];
        #pragma unroll
        for (int k = 0; k < 4; k++) {
            u64 d2 = ffma2(xv, ax2[k], wv);
            d2 = ffma2(yv, ay2[k], d2);
            d2 = ffma2(zv, az2[k], d2);
            float2 d = up2(d2);
            if (d.x < best[k]) { best[k] = d.x; bi[k] = 2 * j; }
            if (d.y < best[k]) { best[k] = d.y; bi[k] = 2 * j + 1; }
        }
    }

    #pragma unroll
    for (int k = 0; k < 4; k++) {
        g_bd[half][s[k]] = best[k];
        g_bi[half][s[k]] = half * 2048 + bi[k];
    }
}

// ---------------- combine halves + gather + weighted sum --------------------
__global__ __launch_bounds__(256)
void gather_kernel()
{
    const int g    = (blockIdx.x * 256 + threadIdx.x) >> 5;  // bq*8 + m
    const int lane = threadIdx.x & 31;
    const int m  = g & 7;
    const int bq = g >> 3;
    const int b  = bq >> 10;
    const int base = bq * 32 + m * 4;
    float acc = 0.0f;
    #pragma unroll
    for (int p = 0; p < 4; p++) {
        int sp = base + p;
        float d0 = g_bd[0][sp], d1 = g_bd[1][sp];
        int l = (d0 <= d1) ? g_bi[0][sp] : g_bi[1][sp];  // tie -> half 0 (lower idx)
        acc += g_attw[sp] * g_value[(b * LIN + l) * CC + m * 32 + lane];
    }
    g_mid[bq * CC + m * 32 + lane] = acc;
}

// ---------------------------------------------------------------------------
extern "C" void kernel_launch(void* const* d_in, const int* in_sizes, int n_in,
                              void* d_out, int out_size) {
    const float* query = (const float*)d_in[0];
    const float* qpts  = (const float*)d_in[1];
    const float* inp   = (const float*)d_in[2];
    const float* ipts  = (const float*)d_in[3];
    const float* Wv    = (const float*)d_in[4];
    const float* bv    = (const float*)d_in[5];
    const float* Ws    = (const float*)d_in[6];
    const float* bs    = (const float*)d_in[7];
    const float* Wa    = (const float*)d_in[8];
    const float* ba    = (const float*)d_in[9];
    const float* Wo    = (const float*)d_in[10];
    const float* bo    = (const float*)d_in[11];
    float* out = (float*)d_out;

    float *p_value, *p_mid;
    cudaGetSymbolAddress((void**)&p_value, g_value);
    cudaGetSymbolAddress((void**)&p_mid,   g_mid);

    const int BIG = 1 << 30;

    // 1) fused sampling-offset + attention projection (writes g_loc / g_attw)
    sgemm_nt<1><<<dim3(2, 32), 256>>>(query, Ws, Wa, 96, bs, ba,
                                      nullptr, 128, qpts);
    // 2) brute-force 1-NN (2 candidate halves per point)
    knn_kernel<<<128, 256>>>(ipts);
    // 3) value projection: 8192x256x256, one full wave of 128 blocks
    sgemm128<<<dim3(2, 64), 256>>>(inp, Wv, bv, p_value, 256);
    // 4) combine + gather + weighted sum
    gather_kernel<<<2048, 256>>>();
    // 5) output projection
    sgemm_nt<0><<<dim3(4, 32), 256>>>(p_mid, Wo, Wo, BIG, bo, bo,
                                      out, 256, nullptr);
}